// round 3
// baseline (speedup 1.0000x reference)
#include <cuda_runtime.h>
#include <cuda_bf16.h>

#define BB 8
#define TT 4
#define NN 4096
#define FIN 3
#define UU 64
#define DOUT 3
#define EE 65536
#define EF (EE + NN)          // edges + self loops = 69632
#define BN (BB * NN)          // 32768

// ---------------- device scratch (no allocations allowed) ----------------
__device__ float g_h[BN * UU];      // GRU hidden state
__device__ float g_hgat[BN * UU];   // z @ gat_W
__device__ float g_s[BN * UU];      // GAT output s
__device__ float g_es[BN];
__device__ float g_ed[BN];
__device__ int   g_cnt[NN];
__device__ int   g_cur[NN];
__device__ int   g_off[NN + 1];
__device__ int   g_srcs[EF];        // CSR: src sorted by dst

// ---------------- preprocessing ----------------
__global__ void zero_kernel() {
    int i = blockIdx.x * blockDim.x + threadIdx.x;
    if (i < BN * UU) g_h[i] = 0.0f;
    if (i < NN) { g_cnt[i] = 0; g_cur[i] = 0; }
}

__global__ void count_kernel(const int* __restrict__ dst) {
    int i = blockIdx.x * blockDim.x + threadIdx.x;
    if (i >= EF) return;
    int d = (i < EE) ? dst[i] : (i - EE);
    atomicAdd(&g_cnt[d], 1);
}

__global__ void scan_kernel() {
    __shared__ int tsum[1024];
    int tid = threadIdx.x;
    int base = tid * 4;
    int c0 = g_cnt[base + 0], c1 = g_cnt[base + 1];
    int c2 = g_cnt[base + 2], c3 = g_cnt[base + 3];
    int sum4 = c0 + c1 + c2 + c3;
    tsum[tid] = sum4;
    __syncthreads();
    for (int ofs = 1; ofs < 1024; ofs <<= 1) {
        int add = 0;
        if (tid >= ofs) add = tsum[tid - ofs];
        __syncthreads();
        tsum[tid] += add;
        __syncthreads();
    }
    int excl = tsum[tid] - sum4;
    g_off[base + 0] = excl;
    g_off[base + 1] = excl + c0;
    g_off[base + 2] = excl + c0 + c1;
    g_off[base + 3] = excl + c0 + c1 + c2;
    if (tid == 1023) g_off[NN] = tsum[1023];
}

__global__ void scatter_kernel(const int* __restrict__ src, const int* __restrict__ dst) {
    int i = blockIdx.x * blockDim.x + threadIdx.x;
    if (i >= EF) return;
    int s, d;
    if (i < EE) { s = src[i]; d = dst[i]; }
    else        { s = i - EE; d = i - EE; }
    int pos = g_off[d] + atomicAdd(&g_cur[d], 1);
    g_srcs[pos] = s;
}

// ---------------- per-timestep kernels ----------------

// A: hgat = [h, x_t] @ gat_W ; es = hgat.a_src ; ed = hgat.a_dst
// 512 threads = 8 nodes/block, 64 threads per node (one per output col)
__global__ __launch_bounds__(512) void gat_node_kernel(
    const float* __restrict__ x, const float* __restrict__ gat_W,
    const float* __restrict__ a_src, const float* __restrict__ a_dst, int t)
{
    __shared__ float sW[67 * 64];
    __shared__ float sa[128];
    __shared__ float sz[8][68];
    __shared__ float sES[8], sED[8];

    int tid = threadIdx.x;
    int g = tid >> 6, j = tid & 63;
    for (int i = tid; i < 67 * 64; i += 512) sW[i] = gat_W[i];
    if (tid < 128) sa[tid] = (tid < 64) ? a_src[tid] : a_dst[tid - 64];
    if (tid < 8) { sES[tid] = 0.0f; sED[tid] = 0.0f; }

    int nid = blockIdx.x * 8 + g;
    int b = nid >> 12, n = nid & 4095;
    sz[g][j] = g_h[nid * 64 + j];
    if (j < 3) sz[g][64 + j] = x[((b * TT + t) * NN + n) * 3 + j];
    __syncthreads();

    float acc = 0.0f;
    #pragma unroll
    for (int k = 0; k < 67; k++) acc += sz[g][k] * sW[k * 64 + j];
    g_hgat[nid * 64 + j] = acc;

    float v1 = acc * sa[j];
    float v2 = acc * sa[64 + j];
    #pragma unroll
    for (int o = 16; o > 0; o >>= 1) {
        v1 += __shfl_down_sync(0xFFFFFFFFu, v1, o);
        v2 += __shfl_down_sync(0xFFFFFFFFu, v2, o);
    }
    if ((tid & 31) == 0) { atomicAdd(&sES[g], v1); atomicAdd(&sED[g], v2); }
    __syncthreads();
    if (j == 0) { g_es[nid] = sES[g]; g_ed[nid] = sED[g]; }
}

// B: gather-based segment softmax + aggregate. One warp per (b, dst).
__global__ __launch_bounds__(256) void gat_gather_kernel(const float* __restrict__ gat_b)
{
    int gw = blockIdx.x * 8 + (threadIdx.x >> 5);
    int lane = threadIdx.x & 31;
    int b = gw >> 12, n = gw & 4095;
    float edv = g_ed[b * NN + n];
    int beg = g_off[n], end = g_off[n + 1];
    float S = 0.0f, a0 = 0.0f, a1 = 0.0f;
    for (int e = beg; e < end; e++) {
        int s = g_srcs[e];
        float ev = g_es[b * NN + s] + edv;
        ev = (ev > 0.0f) ? ev : 0.2f * ev;      // leaky_relu(0.2)
        float w = __expf(ev);
        S += w;
        const float* hg = g_hgat + (b * NN + s) * 64;
        a0 += w * hg[lane];
        a1 += w * hg[lane + 32];
    }
    float inv = 1.0f / S;
    int base = (b * NN + n) * 64;
    g_s[base + lane]      = a0 * inv + gat_b[lane];
    g_s[base + 32 + lane] = a1 * inv + gat_b[lane + 32];
}

// C: GRU cell. 512 threads = 8 nodes/block; smem weight buffer reused W1->W2.
__global__ __launch_bounds__(512) void gru_kernel(
    const float* __restrict__ x,
    const float* __restrict__ W1, const float* __restrict__ b1,
    const float* __restrict__ W2, const float* __restrict__ b2, int t)
{
    __shared__ float sW[67 * 128];  // 34 KB, reused for W2 (67*64)
    __shared__ float sx[8][4];
    __shared__ float ss[8][64];
    __shared__ float srs[8][64];

    int tid = threadIdx.x;
    int g = tid >> 6, j = tid & 63;
    int nid = blockIdx.x * 8 + g;
    int b = nid >> 12, n = nid & 4095;

    for (int i = tid; i < 67 * 128; i += 512) sW[i] = W1[i];
    ss[g][j] = g_s[nid * 64 + j];
    if (j < 3) sx[g][j] = x[((b * TT + t) * NN + n) * 3 + j];
    __syncthreads();

    // ru = sigmoid([x, s] @ W1 + b1); r = col j, u = col j+64
    float ar = b1[j], au = b1[64 + j];
    #pragma unroll
    for (int k = 0; k < 3; k++) {
        float z = sx[g][k];
        ar += z * sW[k * 128 + j];
        au += z * sW[k * 128 + 64 + j];
    }
    #pragma unroll
    for (int k = 0; k < 64; k++) {
        float z = ss[g][k];
        ar += z * sW[(3 + k) * 128 + j];
        au += z * sW[(3 + k) * 128 + 64 + j];
    }
    float r = 1.0f / (1.0f + __expf(-ar));
    float u = 1.0f / (1.0f + __expf(-au));
    float sval = ss[g][j];
    srs[g][j] = r * sval;
    __syncthreads();

    for (int i = tid; i < 67 * 64; i += 512) sW[i] = W2[i];
    __syncthreads();

    // c = tanh([x, r*s] @ W2 + b2)
    float ac = b2[j];
    #pragma unroll
    for (int k = 0; k < 3; k++) ac += sx[g][k] * sW[k * 64 + j];
    #pragma unroll
    for (int k = 0; k < 64; k++) ac += srs[g][k] * sW[(3 + k) * 64 + j];
    float c = tanhf(ac);
    g_h[nid * 64 + j] = u * sval + (1.0f - u) * c;
}

// D: out = h @ out_W + out_b. One warp per node.
__global__ __launch_bounds__(256) void out_kernel(
    const float* __restrict__ oW, const float* __restrict__ ob,
    float* __restrict__ out)
{
    int gw = blockIdx.x * 8 + (threadIdx.x >> 5);
    int lane = threadIdx.x & 31;
    float v0 = g_h[gw * 64 + lane];
    float v1 = g_h[gw * 64 + 32 + lane];
    #pragma unroll
    for (int d = 0; d < 3; d++) {
        float p = v0 * __ldg(&oW[lane * 3 + d]) + v1 * __ldg(&oW[(lane + 32) * 3 + d]);
        #pragma unroll
        for (int o = 16; o > 0; o >>= 1) p += __shfl_down_sync(0xFFFFFFFFu, p, o);
        if (lane == 0) out[gw * 3 + d] = p + ob[d];
    }
}

// ---------------- launch ----------------
extern "C" void kernel_launch(void* const* d_in, const int* in_sizes, int n_in,
                              void* d_out, int out_size)
{
    const float* x       = (const float*)d_in[0];
    const int*   src     = (const int*)  d_in[1];
    const int*   dst     = (const int*)  d_in[2];
    const float* gat_W   = (const float*)d_in[3];
    const float* a_src   = (const float*)d_in[4];
    const float* a_dst   = (const float*)d_in[5];
    const float* gat_b   = (const float*)d_in[6];
    const float* gru1_W  = (const float*)d_in[7];
    const float* gru1_b  = (const float*)d_in[8];
    const float* gru2_W  = (const float*)d_in[9];
    const float* gru2_b  = (const float*)d_in[10];
    const float* out_W   = (const float*)d_in[11];
    const float* out_b   = (const float*)d_in[12];
    float* out = (float*)d_out;

    // init state + CSR build
    zero_kernel<<<(BN * UU + 1023) / 1024, 1024>>>();
    count_kernel<<<(EF + 255) / 256, 256>>>(dst);
    scan_kernel<<<1, 1024>>>();
    scatter_kernel<<<(EF + 255) / 256, 256>>>(src, dst);

    for (int t = 0; t < TT; t++) {
        gat_node_kernel<<<BN / 8, 512>>>(x, gat_W, a_src, a_dst, t);
        gat_gather_kernel<<<BN / 8, 256>>>(gat_b);
        gru_kernel<<<BN / 8, 512>>>(x, gru1_W, gru1_b, gru2_W, gru2_b, t);
    }
    out_kernel<<<BN / 8, 256>>>(out_W, out_b, out);
}

// round 4
// speedup vs baseline: 1.8735x; 1.8735x over previous
#include <cuda_runtime.h>
#include <cuda_bf16.h>

#define BB 8
#define TT 4
#define NN 4096
#define FIN 3
#define UU 64
#define DOUT 3
#define EE 65536
#define EF (EE + NN)          // edges + self loops = 69632
#define BN (BB * NN)          // 32768

// ---------------- device scratch (no allocations allowed) ----------------
__device__ float g_h[BN * UU];      // GRU hidden state
__device__ float g_hgat[BN * UU];   // z @ gat_W
__device__ float g_s[BN * UU];      // GAT output s
__device__ float g_es[BN];
__device__ float g_ed[BN];
__device__ int   g_cnt[NN];
__device__ int   g_cur[NN];
__device__ int   g_off[NN + 1];
__device__ int   g_srcs[EF];        // CSR: src sorted by dst

// ---------------- preprocessing ----------------
__global__ void zero_kernel() {
    int i = blockIdx.x * blockDim.x + threadIdx.x;
    if (i < BN * UU) g_h[i] = 0.0f;
    if (i < NN) { g_cnt[i] = 0; g_cur[i] = 0; }
}

__global__ void count_kernel(const int* __restrict__ dst) {
    int i = blockIdx.x * blockDim.x + threadIdx.x;
    if (i >= EF) return;
    int d = (i < EE) ? dst[i] : (i - EE);
    atomicAdd(&g_cnt[d], 1);
}

__global__ void scan_kernel() {
    __shared__ int tsum[1024];
    int tid = threadIdx.x;
    int base = tid * 4;
    int c0 = g_cnt[base + 0], c1 = g_cnt[base + 1];
    int c2 = g_cnt[base + 2], c3 = g_cnt[base + 3];
    int sum4 = c0 + c1 + c2 + c3;
    tsum[tid] = sum4;
    __syncthreads();
    for (int ofs = 1; ofs < 1024; ofs <<= 1) {
        int add = 0;
        if (tid >= ofs) add = tsum[tid - ofs];
        __syncthreads();
        tsum[tid] += add;
        __syncthreads();
    }
    int excl = tsum[tid] - sum4;
    g_off[base + 0] = excl;
    g_off[base + 1] = excl + c0;
    g_off[base + 2] = excl + c0 + c1;
    g_off[base + 3] = excl + c0 + c1 + c2;
    if (tid == 1023) g_off[NN] = tsum[1023];
}

__global__ void scatter_kernel(const int* __restrict__ src, const int* __restrict__ dst) {
    int i = blockIdx.x * blockDim.x + threadIdx.x;
    if (i >= EF) return;
    int s, d;
    if (i < EE) { s = src[i]; d = dst[i]; }
    else        { s = i - EE; d = i - EE; }
    int pos = g_off[d] + atomicAdd(&g_cur[d], 1);
    g_srcs[pos] = s;
}

// ---------------- per-timestep kernels ----------------

// A: hgat = [h, x_t] @ gat_W ; es = hgat.a_src ; ed = hgat.a_dst
// 256 threads, 64 nodes/block. Each thread: 4-node x 4-col register tile.
__global__ __launch_bounds__(256) void gat_node_kernel(
    const float* __restrict__ x, const float* __restrict__ gat_W,
    const float* __restrict__ a_src, const float* __restrict__ a_dst, int t)
{
    __shared__ float sW[67 * 64];     // 17.2 KB
    __shared__ float sz[64][68];      // [h(64), x(3)] per node, 17.4 KB
    __shared__ float sa[128];

    int tid = threadIdx.x;
    // W: 4288 floats = 1072 float4
    for (int i = tid; i < 1072; i += 256)
        ((float4*)sW)[i] = ((const float4*)gat_W)[i];
    if (tid < 128) sa[tid] = (tid < 64) ? a_src[tid] : a_dst[tid - 64];

    int nbase = blockIdx.x * 64;
    // h: 64 nodes x 16 float4 (coalesced)
    for (int i = tid; i < 1024; i += 256) {
        int ln = i >> 4, kq = i & 15;
        float4 v = ((const float4*)g_h)[(nbase + ln) * 16 + kq];
        sz[ln][kq * 4 + 0] = v.x; sz[ln][kq * 4 + 1] = v.y;
        sz[ln][kq * 4 + 2] = v.z; sz[ln][kq * 4 + 3] = v.w;
    }
    if (tid < 192) {
        int ln = tid / 3, f = tid % 3;
        int nid = nbase + ln;
        int b = nid >> 12, n = nid & 4095;
        sz[ln][64 + f] = x[((b * TT + t) * NN + n) * 3 + f];
    }
    __syncthreads();

    int j4 = (tid & 15) * 4;      // output columns j4..j4+3
    int g  = tid >> 4;            // node group: nodes g*4..g*4+3
    float acc[4][4];
    #pragma unroll
    for (int i = 0; i < 4; i++)
        #pragma unroll
        for (int c = 0; c < 4; c++) acc[i][c] = 0.0f;

    #pragma unroll 4
    for (int k = 0; k < 67; k++) {
        float4 w = *(float4*)&sW[k * 64 + j4];
        #pragma unroll
        for (int i = 0; i < 4; i++) {
            float z = sz[g * 4 + i][k];
            acc[i][0] += z * w.x; acc[i][1] += z * w.y;
            acc[i][2] += z * w.z; acc[i][3] += z * w.w;
        }
    }

    #pragma unroll
    for (int i = 0; i < 4; i++) {
        int nid = nbase + g * 4 + i;
        float4 o = make_float4(acc[i][0], acc[i][1], acc[i][2], acc[i][3]);
        ((float4*)g_hgat)[nid * 16 + (j4 >> 2)] = o;

        float v1 = acc[i][0] * sa[j4]      + acc[i][1] * sa[j4 + 1]
                 + acc[i][2] * sa[j4 + 2]  + acc[i][3] * sa[j4 + 3];
        float v2 = acc[i][0] * sa[64 + j4]     + acc[i][1] * sa[64 + j4 + 1]
                 + acc[i][2] * sa[64 + j4 + 2] + acc[i][3] * sa[64 + j4 + 3];
        #pragma unroll
        for (int o2 = 8; o2 > 0; o2 >>= 1) {
            v1 += __shfl_down_sync(0xFFFFFFFFu, v1, o2, 16);
            v2 += __shfl_down_sync(0xFFFFFFFFu, v2, o2, 16);
        }
        if ((tid & 15) == 0) { g_es[nid] = v1; g_ed[nid] = v2; }
    }
}

// B: gather-based segment softmax + aggregate. One warp per (b, dst).
__global__ __launch_bounds__(256) void gat_gather_kernel(const float* __restrict__ gat_b)
{
    int gw = blockIdx.x * 8 + (threadIdx.x >> 5);
    int lane = threadIdx.x & 31;
    int b = gw >> 12, n = gw & 4095;
    float edv = g_ed[b * NN + n];
    int beg = g_off[n], end = g_off[n + 1];
    float S = 0.0f, a0 = 0.0f, a1 = 0.0f;
    for (int e = beg; e < end; e++) {
        int s = g_srcs[e];
        float ev = g_es[b * NN + s] + edv;
        ev = (ev > 0.0f) ? ev : 0.2f * ev;      // leaky_relu(0.2)
        float w = __expf(ev);
        S += w;
        const float* hg = g_hgat + (b * NN + s) * 64;
        a0 += w * hg[lane];
        a1 += w * hg[lane + 32];
    }
    float inv = 1.0f / S;
    int base = (b * NN + n) * 64;
    g_s[base + lane]      = a0 * inv + gat_b[lane];
    g_s[base + 32 + lane] = a1 * inv + gat_b[lane + 32];
}

// C: GRU cell. 256 threads, 32 nodes/block, register-tiled.
// Phase 1: ru = sigmoid([x,s]@W1+b1) with 4-node x 4-col tiles (128 cols).
// Phase 2: c = tanh([x,r*s]@W2+b2) with 2-node x 4-col tiles (64 cols).
// srs/su alias into the upper (dead) half of the W1 smem buffer.
__global__ __launch_bounds__(256) void gru_kernel(
    const float* __restrict__ x,
    const float* __restrict__ W1, const float* __restrict__ b1,
    const float* __restrict__ W2, const float* __restrict__ b2, int t)
{
    __shared__ float sW[67 * 128];    // 34.3 KB, phase2 reuses lower 67*64
    __shared__ float sz[32][68];      // [x(3), s(64)] per node
    __shared__ float sb1[128];
    __shared__ float sb2[64];
    float* srs = sW + 67 * 64;                 // 2048 floats (r*s)
    float* su  = sW + 67 * 64 + 32 * 64;       // 2048 floats (u)

    int tid = threadIdx.x;
    int nbase = blockIdx.x * 32;

    for (int i = tid; i < 2144; i += 256)
        ((float4*)sW)[i] = ((const float4*)W1)[i];
    if (tid < 128) sb1[tid] = b1[tid];
    if (tid < 64)  sb2[tid] = b2[tid];

    // s: 32 nodes x 16 float4
    for (int i = tid; i < 512; i += 256) {
        int ln = i >> 4, kq = (i & 15) * 4;
        float4 v = ((const float4*)g_s)[(nbase + ln) * 16 + (i & 15)];
        sz[ln][3 + kq + 0] = v.x; sz[ln][3 + kq + 1] = v.y;
        sz[ln][3 + kq + 2] = v.z; sz[ln][3 + kq + 3] = v.w;
    }
    if (tid < 96) {
        int ln = tid / 3, f = tid % 3;
        int nid = nbase + ln;
        int b = nid >> 12, n = nid & 4095;
        sz[ln][f] = x[((b * TT + t) * NN + n) * 3 + f];
    }
    __syncthreads();

    // ---- phase 1: [x,s] @ W1 (67 x 128) ----
    int j4 = (tid & 31) * 4;      // 0..124
    int g  = tid >> 5;            // 0..7, nodes g*4..g*4+3
    float acc[4][4];
    #pragma unroll
    for (int i = 0; i < 4; i++)
        #pragma unroll
        for (int c = 0; c < 4; c++) acc[i][c] = sb1[j4 + c];

    #pragma unroll 4
    for (int k = 0; k < 67; k++) {
        float4 w = *(float4*)&sW[k * 128 + j4];
        #pragma unroll
        for (int i = 0; i < 4; i++) {
            float z = sz[g * 4 + i][k];
            acc[i][0] += z * w.x; acc[i][1] += z * w.y;
            acc[i][2] += z * w.z; acc[i][3] += z * w.w;
        }
    }
    __syncthreads();   // everyone done reading W1 before aliasing its buffer

    // write r*s / u into aliased region; concurrently load W2 into lower region
    #pragma unroll
    for (int i = 0; i < 4; i++) {
        int n = g * 4 + i;
        #pragma unroll
        for (int c = 0; c < 4; c++) {
            float v = 1.0f / (1.0f + __expf(-acc[i][c]));
            if (j4 < 64) srs[n * 64 + j4 + c] = v * sz[n][3 + j4 + c];
            else         su[n * 64 + (j4 - 64) + c] = v;
        }
    }
    for (int i = tid; i < 1072; i += 256)
        ((float4*)sW)[i] = ((const float4*)W2)[i];
    __syncthreads();

    // ---- phase 2: [x, r*s] @ W2 (67 x 64) ----
    int j4b = (tid & 15) * 4;     // 0..60
    int g2  = tid >> 4;           // 0..15, nodes g2*2..g2*2+1
    float a2[2][4];
    #pragma unroll
    for (int i = 0; i < 2; i++)
        #pragma unroll
        for (int c = 0; c < 4; c++) a2[i][c] = sb2[j4b + c];

    #pragma unroll
    for (int k = 0; k < 3; k++) {
        float4 w = *(float4*)&sW[k * 64 + j4b];
        #pragma unroll
        for (int i = 0; i < 2; i++) {
            float z = sz[g2 * 2 + i][k];
            a2[i][0] += z * w.x; a2[i][1] += z * w.y;
            a2[i][2] += z * w.z; a2[i][3] += z * w.w;
        }
    }
    #pragma unroll 4
    for (int k = 0; k < 64; k++) {
        float4 w = *(float4*)&sW[(3 + k) * 64 + j4b];
        #pragma unroll
        for (int i = 0; i < 2; i++) {
            float z = srs[(g2 * 2 + i) * 64 + k];
            a2[i][0] += z * w.x; a2[i][1] += z * w.y;
            a2[i][2] += z * w.z; a2[i][3] += z * w.w;
        }
    }

    #pragma unroll
    for (int i = 0; i < 2; i++) {
        int n = g2 * 2 + i;
        int nid = nbase + n;
        float4 o;
        float cc, u, s;
        cc = tanhf(a2[i][0]); u = su[n * 64 + j4b + 0]; s = sz[n][3 + j4b + 0];
        o.x = u * s + (1.0f - u) * cc;
        cc = tanhf(a2[i][1]); u = su[n * 64 + j4b + 1]; s = sz[n][3 + j4b + 1];
        o.y = u * s + (1.0f - u) * cc;
        cc = tanhf(a2[i][2]); u = su[n * 64 + j4b + 2]; s = sz[n][3 + j4b + 2];
        o.z = u * s + (1.0f - u) * cc;
        cc = tanhf(a2[i][3]); u = su[n * 64 + j4b + 3]; s = sz[n][3 + j4b + 3];
        o.w = u * s + (1.0f - u) * cc;
        ((float4*)g_h)[nid * 16 + (j4b >> 2)] = o;
    }
}

// D: out = h @ out_W + out_b. One warp per node.
__global__ __launch_bounds__(256) void out_kernel(
    const float* __restrict__ oW, const float* __restrict__ ob,
    float* __restrict__ out)
{
    int gw = blockIdx.x * 8 + (threadIdx.x >> 5);
    int lane = threadIdx.x & 31;
    float v0 = g_h[gw * 64 + lane];
    float v1 = g_h[gw * 64 + 32 + lane];
    #pragma unroll
    for (int d = 0; d < 3; d++) {
        float p = v0 * __ldg(&oW[lane * 3 + d]) + v1 * __ldg(&oW[(lane + 32) * 3 + d]);
        #pragma unroll
        for (int o = 16; o > 0; o >>= 1) p += __shfl_down_sync(0xFFFFFFFFu, p, o);
        if (lane == 0) out[gw * 3 + d] = p + ob[d];
    }
}

// ---------------- launch ----------------
extern "C" void kernel_launch(void* const* d_in, const int* in_sizes, int n_in,
                              void* d_out, int out_size)
{
    const float* x       = (const float*)d_in[0];
    const int*   src     = (const int*)  d_in[1];
    const int*   dst     = (const int*)  d_in[2];
    const float* gat_W   = (const float*)d_in[3];
    const float* a_src   = (const float*)d_in[4];
    const float* a_dst   = (const float*)d_in[5];
    const float* gat_b   = (const float*)d_in[6];
    const float* gru1_W  = (const float*)d_in[7];
    const float* gru1_b  = (const float*)d_in[8];
    const float* gru2_W  = (const float*)d_in[9];
    const float* gru2_b  = (const float*)d_in[10];
    const float* out_W   = (const float*)d_in[11];
    const float* out_b   = (const float*)d_in[12];
    float* out = (float*)d_out;

    // init state + CSR build
    zero_kernel<<<(BN * UU + 1023) / 1024, 1024>>>();
    count_kernel<<<(EF + 255) / 256, 256>>>(dst);
    scan_kernel<<<1, 1024>>>();
    scatter_kernel<<<(EF + 255) / 256, 256>>>(src, dst);

    for (int t = 0; t < TT; t++) {
        gat_node_kernel<<<BN / 64, 256>>>(x, gat_W, a_src, a_dst, t);
        gat_gather_kernel<<<BN / 8, 256>>>(gat_b);
        gru_kernel<<<BN / 32, 256>>>(x, gru1_W, gru1_b, gru2_W, gru2_b, t);
    }
    out_kernel<<<BN / 8, 256>>>(out_W, out_b, out);
}